// round 3
// baseline (speedup 1.0000x reference)
#include <cuda_runtime.h>
#include <cstdint>

// Problem sizes (fixed by dataset)
#define TOK    8192      // B*S
#define DDIM   1024
#define NPOOL  64
#define RDIM   128

// h partials: [2 n-halves][TOK][RDIM]  (8 MB static device scratch)
__device__ float g_h[2u * TOK * RDIM];

// ---------------- helpers ----------------
__device__ __forceinline__ uint32_t smem_u32(const void* p) {
    uint32_t a;
    asm("{ .reg .u64 t; cvta.to.shared.u64 t, %1; cvt.u32.u64 %0, t; }" : "=r"(a) : "l"(p));
    return a;
}
__device__ __forceinline__ uint32_t f2tf32(float f) {
    uint32_t u;
    asm("cvt.rna.tf32.f32 %0, %1;" : "=r"(u) : "f"(f));
    return u;
}
__device__ __forceinline__ void cp_async16(uint32_t smem_dst, const void* gptr) {
    asm volatile("cp.async.cg.shared.global [%0], [%1], 16;" :: "r"(smem_dst), "l"(gptr) : "memory");
}
__device__ __forceinline__ void cp_commit() { asm volatile("cp.async.commit_group;" ::: "memory"); }
__device__ __forceinline__ void cp_wait0()  { asm volatile("cp.async.wait_group 0;" ::: "memory"); }

__device__ __forceinline__ void mma_tf32(float* c, const uint32_t* a, uint32_t b0, uint32_t b1) {
    asm volatile(
        "mma.sync.aligned.m16n8k8.row.col.f32.tf32.tf32.f32 "
        "{%0,%1,%2,%3}, {%4,%5,%6,%7}, {%8,%9}, {%0,%1,%2,%3};"
        : "+f"(c[0]), "+f"(c[1]), "+f"(c[2]), "+f"(c[3])
        : "r"(a[0]), "r"(a[1]), "r"(a[2]), "r"(a[3]), "r"(b0), "r"(b1));
}

// Swizzled SMEM indexing (float units). Conflict-free for all access patterns used.
// A: [m][k], 128 x 32 ;  B: [k][n], 32 x 128
#define AIDX(m, k) ((m) * 32 + ((k) ^ (((m) & 7) << 2)))
#define BIDX(k, n) ((k) * 128 + ((n) ^ (((k) & 3) << 3)))

// SMEM layout (floats): A0[4096] B0[4096] A1[4096] B1[4096] -> 64KB
#define SM_A(buf) ((buf) * 8192)
#define SM_B(buf) ((buf) * 8192 + 4096)
#define SMEM_BYTES (65536)

// ---------------- shared compute core ----------------
// 8 warps: warp (wid&3) -> rows (wid&3)*32 ; (wid>>2) -> cols (wid>>2)*64
// C layout per warp: c[2 mtiles][8 ntiles][4]
struct Frag { float c[2][8][4]; };

__device__ __forceinline__ void compute_chunk(const uint32_t* __restrict__ As,
                                              const uint32_t* __restrict__ Bs,
                                              int wid, int lane, Frag& F) {
    int mrow = (wid & 3) * 32;
    int ncol = (wid >> 2) * 64;
    int rA = mrow + (lane >> 2);
    int cA = lane & 3;
    int nB = lane >> 2;
    int kB = lane & 3;
    #pragma unroll
    for (int ks = 0; ks < 4; ++ks) {
        int k0 = ks * 8;
        uint32_t a[2][4];
        #pragma unroll
        for (int mt = 0; mt < 2; ++mt) {
            int m = rA + mt * 16;
            a[mt][0] = As[AIDX(m, k0 + cA)];
            a[mt][1] = As[AIDX(m + 8, k0 + cA)];
            a[mt][2] = As[AIDX(m, k0 + 4 + cA)];
            a[mt][3] = As[AIDX(m + 8, k0 + 4 + cA)];
        }
        #pragma unroll
        for (int nt = 0; nt < 8; ++nt) {
            uint32_t b0 = Bs[BIDX(k0 + kB, ncol + nt * 8 + nB)];
            uint32_t b1 = Bs[BIDX(k0 + 4 + kB, ncol + nt * 8 + nB)];
            mma_tf32(F.c[0][nt], a[0], b0, b1);
            mma_tf32(F.c[1][nt], a[1], b0, b1);
        }
    }
}

// ==================== Stage 1 ====================
// grid (64 token-tiles, 2 n-halves). C[128 tok,128 r] = sum_{n in half, d} (fw.x) @ FK
__global__ __launch_bounds__(256, 1)
void kc_stage1(const float* __restrict__ x, const float* __restrict__ fw,
               const float* __restrict__ FK) {
    extern __shared__ uint32_t smem[];
    int tid = threadIdx.x, wid = tid >> 5, lane = tid & 31;
    int tok0 = blockIdx.x * 128;
    int half = blockIdx.y;
    int n0 = half * 32;

    const int CHUNKS = 32 * (DDIM / 32);  // 1024

    Frag F;
    #pragma unroll
    for (int mt = 0; mt < 2; ++mt)
        #pragma unroll
        for (int nt = 0; nt < 8; ++nt)
            #pragma unroll
            for (int q = 0; q < 4; ++q) F.c[mt][nt][q] = 0.f;

    uint32_t sbase = smem_u32(smem);

    // ---- prologue: fill chunk 0 into buf 0 ----
    {
        int n = n0, d0 = 0;
        #pragma unroll
        for (int it = 0; it < 4; ++it) {
            int idx = tid + it * 256;
            int m = idx >> 3, g = idx & 7;
            int tok = tok0 + m;
            float w = fw[tok * NPOOL + n];
            float4 v = *(const float4*)&x[(size_t)tok * DDIM + d0 + g * 4];
            uint4 t;
            t.x = f2tf32(v.x * w); t.y = f2tf32(v.y * w);
            t.z = f2tf32(v.z * w); t.w = f2tf32(v.w * w);
            *(uint4*)&smem[SM_A(0) + AIDX(m, g * 4)] = t;
        }
        #pragma unroll
        for (int it = 0; it < 4; ++it) {
            int idx = tid + it * 256;
            int k = idx >> 5, nq = idx & 31;
            const float* src = &FK[((size_t)n * DDIM + d0 + k) * RDIM + nq * 4];
            cp_async16(sbase + 4 * (SM_B(0) + BIDX(k, nq * 4)), src);
        }
        cp_commit();
        cp_wait0();
        __syncthreads();
    }

    float4 vp[4]; float wp[4];
    for (int c = 0; c < CHUNKS; ++c) {
        int buf = c & 1;
        bool more = (c + 1 < CHUNKS);
        if (more) {
            int cn = c + 1;
            int n = n0 + (cn >> 5), d0 = (cn & 31) * 32;
            #pragma unroll
            for (int it = 0; it < 4; ++it) {
                int idx = tid + it * 256;
                int m = idx >> 3, g = idx & 7;
                int tok = tok0 + m;
                wp[it] = fw[tok * NPOOL + n];
                vp[it] = *(const float4*)&x[(size_t)tok * DDIM + d0 + g * 4];
            }
            #pragma unroll
            for (int it = 0; it < 4; ++it) {
                int idx = tid + it * 256;
                int k = idx >> 5, nq = idx & 31;
                const float* src = &FK[((size_t)n * DDIM + d0 + k) * RDIM + nq * 4];
                cp_async16(sbase + 4 * (SM_B(buf ^ 1) + BIDX(k, nq * 4)), src);
            }
            cp_commit();
        }

        compute_chunk(&smem[SM_A(buf)], &smem[SM_B(buf)], wid, lane, F);

        if (more) {
            #pragma unroll
            for (int it = 0; it < 4; ++it) {
                int idx = tid + it * 256;
                int m = idx >> 3, g = idx & 7;
                uint4 t;
                t.x = f2tf32(vp[it].x * wp[it]); t.y = f2tf32(vp[it].y * wp[it]);
                t.z = f2tf32(vp[it].z * wp[it]); t.w = f2tf32(vp[it].w * wp[it]);
                *(uint4*)&smem[SM_A(buf ^ 1) + AIDX(m, g * 4)] = t;
            }
            cp_wait0();
            __syncthreads();
        }
    }

    // ---- epilogue: write h partial ----
    {
        int mrow = tok0 + (wid & 3) * 32;
        int ncol = (wid >> 2) * 64;
        #pragma unroll
        for (int mt = 0; mt < 2; ++mt) {
            int row = mrow + mt * 16 + (lane >> 2);
            #pragma unroll
            for (int nt = 0; nt < 8; ++nt) {
                int col = ncol + nt * 8 + (lane & 3) * 2;
                float* p0 = &g_h[((size_t)half * TOK + row) * RDIM + col];
                float* p1 = &g_h[((size_t)half * TOK + row + 8) * RDIM + col];
                *(float2*)p0 = make_float2(F.c[mt][nt][0], F.c[mt][nt][1]);
                *(float2*)p1 = make_float2(F.c[mt][nt][2], F.c[mt][nt][3]);
            }
        }
    }
}

// ==================== Stage 2 ====================
// grid (64 token-tiles, 8 d-tiles). out[128 tok,128 d] = sum_{n,r} (rw.(h0+h1)) @ RK
__global__ __launch_bounds__(256, 1)
void kc_stage2(const float* __restrict__ rw, const float* __restrict__ RK,
               float* __restrict__ out) {
    extern __shared__ uint32_t smem[];
    int tid = threadIdx.x, wid = tid >> 5, lane = tid & 31;
    int tok0 = blockIdx.x * 128;
    int dt0 = blockIdx.y * 128;

    const int CHUNKS = NPOOL * (RDIM / 32);  // 256

    Frag F;
    #pragma unroll
    for (int mt = 0; mt < 2; ++mt)
        #pragma unroll
        for (int nt = 0; nt < 8; ++nt)
            #pragma unroll
            for (int q = 0; q < 4; ++q) F.c[mt][nt][q] = 0.f;

    uint32_t sbase = smem_u32(smem);

    // ---- prologue: chunk 0 ----
    {
        int n = 0, r0 = 0;
        #pragma unroll
        for (int it = 0; it < 4; ++it) {
            int idx = tid + it * 256;
            int m = idx >> 3, g = idx & 7;
            int tok = tok0 + m;
            float w = rw[tok * NPOOL + n];
            size_t ho = (size_t)tok * RDIM + r0 + g * 4;
            float4 v0 = *(const float4*)&g_h[ho];
            float4 v1 = *(const float4*)&g_h[(size_t)TOK * RDIM + ho];
            uint4 t;
            t.x = f2tf32((v0.x + v1.x) * w); t.y = f2tf32((v0.y + v1.y) * w);
            t.z = f2tf32((v0.z + v1.z) * w); t.w = f2tf32((v0.w + v1.w) * w);
            *(uint4*)&smem[SM_A(0) + AIDX(m, g * 4)] = t;
        }
        #pragma unroll
        for (int it = 0; it < 4; ++it) {
            int idx = tid + it * 256;
            int k = idx >> 5, nq = idx & 31;
            const float* src = &RK[((size_t)n * RDIM + r0 + k) * DDIM + dt0 + nq * 4];
            cp_async16(sbase + 4 * (SM_B(0) + BIDX(k, nq * 4)), src);
        }
        cp_commit();
        cp_wait0();
        __syncthreads();
    }

    float4 v0p[4], v1p[4]; float wp[4];
    for (int c = 0; c < CHUNKS; ++c) {
        int buf = c & 1;
        bool more = (c + 1 < CHUNKS);
        if (more) {
            int cn = c + 1;
            int n = cn >> 2, r0 = (cn & 3) * 32;
            #pragma unroll
            for (int it = 0; it < 4; ++it) {
                int idx = tid + it * 256;
                int m = idx >> 3, g = idx & 7;
                int tok = tok0 + m;
                wp[it] = rw[tok * NPOOL + n];
                size_t ho = (size_t)tok * RDIM + r0 + g * 4;
                v0p[it] = *(const float4*)&g_h[ho];
                v1p[it] = *(const float4*)&g_h[(size_t)TOK * RDIM + ho];
            }
            #pragma unroll
            for (int it = 0; it < 4; ++it) {
                int idx = tid + it * 256;
                int k = idx >> 5, nq = idx & 31;
                const float* src = &RK[((size_t)n * RDIM + r0 + k) * DDIM + dt0 + nq * 4];
                cp_async16(sbase + 4 * (SM_B(buf ^ 1) + BIDX(k, nq * 4)), src);
            }
            cp_commit();
        }

        compute_chunk(&smem[SM_A(buf)], &smem[SM_B(buf)], wid, lane, F);

        if (more) {
            #pragma unroll
            for (int it = 0; it < 4; ++it) {
                int idx = tid + it * 256;
                int m = idx >> 3, g = idx & 7;
                uint4 t;
                t.x = f2tf32((v0p[it].x + v1p[it].x) * wp[it]);
                t.y = f2tf32((v0p[it].y + v1p[it].y) * wp[it]);
                t.z = f2tf32((v0p[it].z + v1p[it].z) * wp[it]);
                t.w = f2tf32((v0p[it].w + v1p[it].w) * wp[it]);
                *(uint4*)&smem[SM_A(buf ^ 1) + AIDX(m, g * 4)] = t;
            }
            cp_wait0();
            __syncthreads();
        }
    }

    // ---- epilogue: write out ----
    {
        int mrow = tok0 + (wid & 3) * 32;
        int ncol = dt0 + (wid >> 2) * 64;
        #pragma unroll
        for (int mt = 0; mt < 2; ++mt) {
            int row = mrow + mt * 16 + (lane >> 2);
            #pragma unroll
            for (int nt = 0; nt < 8; ++nt) {
                int col = ncol + nt * 8 + (lane & 3) * 2;
                float* p0 = &out[(size_t)row * DDIM + col];
                float* p1 = &out[(size_t)(row + 8) * DDIM + col];
                *(float2*)p0 = make_float2(F.c[mt][nt][0], F.c[mt][nt][1]);
                *(float2*)p1 = make_float2(F.c[mt][nt][2], F.c[mt][nt][3]);
            }
        }
    }
}

// ==================== launch ====================
extern "C" void kernel_launch(void* const* d_in, const int* in_sizes, int n_in,
                              void* d_out, int out_size) {
    const float* x  = (const float*)d_in[0];
    const float* fw = (const float*)d_in[1];
    const float* rw = (const float*)d_in[2];
    const float* FK = (const float*)d_in[3];
    const float* RK = (const float*)d_in[4];
    float* out = (float*)d_out;

    cudaFuncSetAttribute(kc_stage1, cudaFuncAttributeMaxDynamicSharedMemorySize, SMEM_BYTES);
    cudaFuncSetAttribute(kc_stage2, cudaFuncAttributeMaxDynamicSharedMemorySize, SMEM_BYTES);

    kc_stage1<<<dim3(64, 2), 256, SMEM_BYTES>>>(x, fw, FK);
    kc_stage2<<<dim3(64, 8), 256, SMEM_BYTES>>>(rw, RK, out);
}

// round 9
// speedup vs baseline: 1.2629x; 1.2629x over previous
#include <cuda_runtime.h>
#include <cstdint>

// Problem sizes (fixed by dataset)
#define TOK    8192      // B*S
#define DDIM   1024
#define NPOOL  64
#define RDIM   128

// h partials: [2 n-halves][TOK][RDIM]  (8 MB static device scratch)
__device__ float g_h[2u * TOK * RDIM];

// ---------------- helpers ----------------
__device__ __forceinline__ uint32_t smem_u32(const void* p) {
    uint32_t a;
    asm("{ .reg .u64 t; cvta.to.shared.u64 t, %1; cvt.u32.u64 %0, t; }" : "=r"(a) : "l"(p));
    return a;
}
__device__ __forceinline__ uint32_t f2tf32(float f) {
    uint32_t u;
    asm("cvt.rna.tf32.f32 %0, %1;" : "=r"(u) : "f"(f));
    return u;
}
__device__ __forceinline__ void cp_async16(uint32_t smem_dst, const void* gptr) {
    asm volatile("cp.async.cg.shared.global [%0], [%1], 16;" :: "r"(smem_dst), "l"(gptr) : "memory");
}
#define MBARRIER_INIT(addr, cnt) \
    asm volatile("mbarrier.init.shared.b64 [%0], %1;" :: "r"((uint32_t)(addr)), "r"((uint32_t)(cnt)) : "memory")
#define MBARRIER_ARRIVE(addr) \
    asm volatile("mbarrier.arrive.shared.b64 _, [%0];" :: "r"((uint32_t)(addr)) : "memory")
// .noinc is load-bearing: default form increments pending count (count-neutral);
// .noinc actually contributes to the expected-arrival count.
#define CP_MBAR_ARRIVE(addr) \
    asm volatile("cp.async.mbarrier.arrive.noinc.shared.b64 [%0];" :: "r"((uint32_t)(addr)) : "memory")

#define MBARRIER_WAIT_PARITY(addr, par) do { \
    uint32_t _m = (uint32_t)(addr), _p = (uint32_t)(par), _d; \
    asm volatile("{ .reg .pred p; mbarrier.try_wait.parity.acquire.cta.shared::cta.b64 p, [%1], %2; selp.b32 %0,1,0,p; }" \
        : "=r"(_d) : "r"(_m), "r"(_p) : "memory"); \
    if (!_d) { \
        asm volatile("{ .reg .pred P1; WL_%=: mbarrier.try_wait.parity.acquire.cta.shared::cta.b64 P1, [%0], %1, 0x989680; @P1 bra.uni WD_%=; bra.uni WL_%=; WD_%=: }" \
            :: "r"(_m), "r"(_p) : "memory"); \
    } } while (0)

__device__ __forceinline__ void mma_tf32(float* c, const uint32_t* a, uint32_t b0, uint32_t b1) {
    asm volatile(
        "mma.sync.aligned.m16n8k8.row.col.f32.tf32.tf32.f32 "
        "{%0,%1,%2,%3}, {%4,%5,%6,%7}, {%8,%9}, {%0,%1,%2,%3};"
        : "+f"(c[0]), "+f"(c[1]), "+f"(c[2]), "+f"(c[3])
        : "r"(a[0]), "r"(a[1]), "r"(a[2]), "r"(a[3]), "r"(b0), "r"(b1));
}

// Swizzled SMEM indexing (float units), conflict-free for all used patterns.
// A: [m][k], 128 x 32 ;  B: [k][n], 32 x 128
#define AIDX(m, k) ((m) * 32 + ((k) ^ (((m) & 7) << 2)))
#define BIDX(k, n) ((k) * 128 + ((n) ^ (((k) & 3) << 3)))

// SMEM: [0..1023] barriers; then 4 stages x (A 16KB + B 16KB)
#define NST 4
#define SM_A(s) (256 + (s) * 8192)          // float offset
#define SM_B(s) (256 + (s) * 8192 + 4096)   // float offset
#define SMEM_BYTES (1024 + NST * 32768)
// barrier byte offsets from smem base: full[s] = s*8 ; empty[s] = 64 + s*8

// ---------------- consumer compute core ----------------
// 8 consumer warps: rows band (wid&3)*32, cols band (wid>>2)*64
struct Frag { float c[2][8][4]; };

__device__ __forceinline__ void compute_chunk(const uint32_t* __restrict__ As,
                                              const uint32_t* __restrict__ Bs,
                                              int wid, int lane, Frag& F) {
    int ncol = (wid >> 2) * 64;
    int rA = (wid & 3) * 32 + (lane >> 2);
    int cA = lane & 3, nB = lane >> 2, kB = lane & 3;
    #pragma unroll
    for (int ks = 0; ks < 4; ++ks) {
        int k0 = ks * 8;
        uint32_t a[2][4], b[8][2];
        #pragma unroll
        for (int nt = 0; nt < 8; ++nt) {
            b[nt][0] = Bs[BIDX(k0 + kB,     ncol + nt * 8 + nB)];
            b[nt][1] = Bs[BIDX(k0 + 4 + kB, ncol + nt * 8 + nB)];
        }
        #pragma unroll
        for (int mt = 0; mt < 2; ++mt) {
            int m = rA + mt * 16;
            a[mt][0] = As[AIDX(m,     k0 + cA)];
            a[mt][1] = As[AIDX(m + 8, k0 + cA)];
            a[mt][2] = As[AIDX(m,     k0 + 4 + cA)];
            a[mt][3] = As[AIDX(m + 8, k0 + 4 + cA)];
        }
        #pragma unroll
        for (int nt = 0; nt < 8; ++nt) {
            mma_tf32(F.c[0][nt], a[0], b[nt][0], b[nt][1]);
            mma_tf32(F.c[1][nt], a[1], b[nt][0], b[nt][1]);
        }
    }
}

// ==================== Stage 1 ====================
// grid (64 token-tiles, 2 n-halves). C[128 tok,128 r] = sum_{n in half, d} (fw.x) @ FK
// chunk c: d-block = c>>5 (outer), n = n0 + (c&31) (inner) -> x cached in producer regs
__global__ __launch_bounds__(384, 1)
void kc_stage1(const float* __restrict__ x, const float* __restrict__ fw,
               const float* __restrict__ FK) {
    extern __shared__ uint32_t smem[];
    uint32_t sb = smem_u32(smem);
    int tid = threadIdx.x, wid = tid >> 5, lane = tid & 31;
    int tok0 = blockIdx.x * 128;
    int n0 = blockIdx.y * 32;
    const int CHUNKS = 32 * 32;  // 32 d-blocks * 32 n

    if (tid == 0) {
        #pragma unroll
        for (int s = 0; s < NST; ++s) {
            MBARRIER_INIT(sb + s * 8, 256);       // full: 128 STS-arrives + 128 cp-noinc-arrives
            MBARRIER_INIT(sb + 64 + s * 8, 256);  // empty: 256 consumer threads
        }
    }
    __syncthreads();

    if (wid >= 8) {
        // ---------------- producer (4 warps, 128 threads) ----------------
        int pt = tid - 256;          // 0..127
        int rbase = pt >> 3;         // 0..15
        int g4 = (pt & 7) * 4;       // col group within 32 k
        float4 xc[8];
        int st = 0, ph = 1;          // parity trick: first NST empty-waits pass
        for (int c = 0; c < CHUNKS; ++c) {
            int d0 = (c >> 5) * 32;
            int n = n0 + (c & 31);
            if ((c & 31) == 0) {     // refresh x cache once per d-block
                #pragma unroll
                for (int p = 0; p < 8; ++p)
                    xc[p] = *(const float4*)&x[(size_t)(tok0 + rbase + 16 * p) * DDIM + d0 + g4];
            }
            MBARRIER_WAIT_PARITY(sb + 64 + st * 8, ph);
            uint32_t* A = smem + SM_A(st);
            #pragma unroll
            for (int p = 0; p < 8; ++p) {
                int m = rbase + 16 * p;
                float w = fw[(tok0 + m) * NPOOL + n];
                uint4 t4;
                t4.x = f2tf32(xc[p].x * w); t4.y = f2tf32(xc[p].y * w);
                t4.z = f2tf32(xc[p].z * w); t4.w = f2tf32(xc[p].w * w);
                *(uint4*)&A[AIDX(m, g4)] = t4;
            }
            MBARRIER_ARRIVE(sb + st * 8);        // releases this thread's STS
            uint32_t bb = sb + 4u * SM_B(st);
            #pragma unroll
            for (int it = 0; it < 8; ++it) {
                int idx = pt + it * 128;
                int k = idx >> 5, nq = idx & 31;
                cp_async16(bb + 4u * BIDX(k, nq * 4),
                           &FK[((size_t)n * DDIM + d0 + k) * RDIM + nq * 4]);
            }
            CP_MBAR_ARRIVE(sb + st * 8);         // arrives when this thread's cp.asyncs land
            if (++st == NST) { st = 0; ph ^= 1; }
        }
        return;
    }

    // ---------------- consumers (8 warps) ----------------
    Frag F;
    #pragma unroll
    for (int mt = 0; mt < 2; ++mt)
        #pragma unroll
        for (int nt = 0; nt < 8; ++nt)
            #pragma unroll
            for (int q = 0; q < 4; ++q) F.c[mt][nt][q] = 0.f;

    {
        int st = 0, ph = 0;
        for (int c = 0; c < CHUNKS; ++c) {
            MBARRIER_WAIT_PARITY(sb + st * 8, ph);
            compute_chunk(smem + SM_A(st), smem + SM_B(st), wid, lane, F);
            MBARRIER_ARRIVE(sb + 64 + st * 8);
            if (++st == NST) { st = 0; ph ^= 1; }
        }
    }

    // epilogue: write h partial
    {
        int mrow = tok0 + (wid & 3) * 32;
        int ncol = (wid >> 2) * 64;
        size_t hb = (size_t)blockIdx.y * TOK;
        #pragma unroll
        for (int mt = 0; mt < 2; ++mt) {
            int row = mrow + mt * 16 + (lane >> 2);
            #pragma unroll
            for (int nt = 0; nt < 8; ++nt) {
                int col = ncol + nt * 8 + (lane & 3) * 2;
                *(float2*)&g_h[(hb + row) * RDIM + col]     = make_float2(F.c[mt][nt][0], F.c[mt][nt][1]);
                *(float2*)&g_h[(hb + row + 8) * RDIM + col] = make_float2(F.c[mt][nt][2], F.c[mt][nt][3]);
            }
        }
    }
}

// ==================== Stage 2 ====================
// grid (64 token-tiles, 8 d-tiles). out[128 tok,128 d] = sum_{n,r} (rw.(h0+h1)) @ RK
// chunk c: r-block = c>>6 (outer), n = c&63 (inner) -> h cached in producer regs
__global__ __launch_bounds__(384, 1)
void kc_stage2(const float* __restrict__ rw, const float* __restrict__ RK,
               float* __restrict__ out) {
    extern __shared__ uint32_t smem[];
    uint32_t sb = smem_u32(smem);
    int tid = threadIdx.x, wid = tid >> 5, lane = tid & 31;
    int tok0 = blockIdx.x * 128;
    int dt0 = blockIdx.y * 128;
    const int CHUNKS = 4 * 64;  // 4 r-blocks * 64 n

    if (tid == 0) {
        #pragma unroll
        for (int s = 0; s < NST; ++s) {
            MBARRIER_INIT(sb + s * 8, 256);
            MBARRIER_INIT(sb + 64 + s * 8, 256);
        }
    }
    __syncthreads();

    if (wid >= 8) {
        // ---------------- producer ----------------
        int pt = tid - 256;
        int rbase = pt >> 3;
        int g4 = (pt & 7) * 4;
        float4 hc[8];
        int st = 0, ph = 1;
        for (int c = 0; c < CHUNKS; ++c) {
            int r0 = (c >> 6) * 32;
            int n = c & 63;
            if ((c & 63) == 0) {     // refresh (h0+h1) cache once per r-block
                #pragma unroll
                for (int p = 0; p < 8; ++p) {
                    size_t ho = (size_t)(tok0 + rbase + 16 * p) * RDIM + r0 + g4;
                    float4 v0 = *(const float4*)&g_h[ho];
                    float4 v1 = *(const float4*)&g_h[(size_t)TOK * RDIM + ho];
                    hc[p] = make_float4(v0.x + v1.x, v0.y + v1.y, v0.z + v1.z, v0.w + v1.w);
                }
            }
            MBARRIER_WAIT_PARITY(sb + 64 + st * 8, ph);
            uint32_t* A = smem + SM_A(st);
            #pragma unroll
            for (int p = 0; p < 8; ++p) {
                int m = rbase + 16 * p;
                float w = rw[(tok0 + m) * NPOOL + n];
                uint4 t4;
                t4.x = f2tf32(hc[p].x * w); t4.y = f2tf32(hc[p].y * w);
                t4.z = f2tf32(hc[p].z * w); t4.w = f2tf32(hc[p].w * w);
                *(uint4*)&A[AIDX(m, g4)] = t4;
            }
            MBARRIER_ARRIVE(sb + st * 8);
            uint32_t bb = sb + 4u * SM_B(st);
            #pragma unroll
            for (int it = 0; it < 8; ++it) {
                int idx = pt + it * 128;
                int k = idx >> 5, nq = idx & 31;
                cp_async16(bb + 4u * BIDX(k, nq * 4),
                           &RK[((size_t)n * RDIM + r0 + k) * DDIM + dt0 + nq * 4]);
            }
            CP_MBAR_ARRIVE(sb + st * 8);
            if (++st == NST) { st = 0; ph ^= 1; }
        }
        return;
    }

    // ---------------- consumers ----------------
    Frag F;
    #pragma unroll
    for (int mt = 0; mt < 2; ++mt)
        #pragma unroll
        for (int nt = 0; nt < 8; ++nt)
            #pragma unroll
            for (int q = 0; q < 4; ++q) F.c[mt][nt][q] = 0.f;

    {
        int st = 0, ph = 0;
        for (int c = 0; c < CHUNKS; ++c) {
            MBARRIER_WAIT_PARITY(sb + st * 8, ph);
            compute_chunk(smem + SM_A(st), smem + SM_B(st), wid, lane, F);
            MBARRIER_ARRIVE(sb + 64 + st * 8);
            if (++st == NST) { st = 0; ph ^= 1; }
        }
    }

    // epilogue: write out
    {
        int mrow = tok0 + (wid & 3) * 32;
        int ncol = dt0 + (wid >> 2) * 64;
        #pragma unroll
        for (int mt = 0; mt < 2; ++mt) {
            int row = mrow + mt * 16 + (lane >> 2);
            #pragma unroll
            for (int nt = 0; nt < 8; ++nt) {
                int col = ncol + nt * 8 + (lane & 3) * 2;
                *(float2*)&out[(size_t)row * DDIM + col]       = make_float2(F.c[mt][nt][0], F.c[mt][nt][1]);
                *(float2*)&out[(size_t)(row + 8) * DDIM + col] = make_float2(F.c[mt][nt][2], F.c[mt][nt][3]);
            }
        }
    }
}

// ==================== launch ====================
extern "C" void kernel_launch(void* const* d_in, const int* in_sizes, int n_in,
                              void* d_out, int out_size) {
    const float* x  = (const float*)d_in[0];
    const float* fw = (const float*)d_in[1];
    const float* rw = (const float*)d_in[2];
    const float* FK = (const float*)d_in[3];
    const float* RK = (const float*)d_in[4];
    float* out = (float*)d_out;

    cudaFuncSetAttribute(kc_stage1, cudaFuncAttributeMaxDynamicSharedMemorySize, SMEM_BYTES);
    cudaFuncSetAttribute(kc_stage2, cudaFuncAttributeMaxDynamicSharedMemorySize, SMEM_BYTES);

    kc_stage1<<<dim3(64, 2), 384, SMEM_BYTES>>>(x, fw, FK);
    kc_stage2<<<dim3(64, 8), 384, SMEM_BYTES>>>(rw, RK, out);
}